// round 6
// baseline (speedup 1.0000x reference)
#include <cuda_runtime.h>
#include <cstdint>

#define NNODES 50000
#define NEDGES 800000
#define HID 128

__device__ float g_agg[(size_t)NNODES * HID];
__device__ float g_h[(size_t)NNODES * HID];
__device__ float g_colsum[HID];
__device__ float g_b1adj[HID];
__device__ int g_is64;  // 1 if edge_index is int64, 0 if int32

// ---------------------------------------------------------------------------
// Detect edge_index dtype (int64 values < 2^31 have zero odd int32 words).
// ---------------------------------------------------------------------------
__global__ void detect_kernel(const int* __restrict__ ei32) {
    __shared__ int nz;
    if (threadIdx.x == 0) nz = 0;
    __syncthreads();
    int cnt = 0;
    for (int i = threadIdx.x; i < 1024; i += blockDim.x)
        if (ei32[2 * i + 1] != 0) cnt++;
    atomicAdd(&nz, cnt);
    __syncthreads();
    if (threadIdx.x == 0) g_is64 = (nz == 0) ? 1 : 0;
}

__global__ void zero_kernel() {
    size_t total = (size_t)NNODES * HID;
    for (size_t i = (size_t)blockIdx.x * blockDim.x + threadIdx.x; i < total;
         i += (size_t)gridDim.x * blockDim.x)
        g_agg[i] = 0.0f;
    if (blockIdx.x == 0 && threadIdx.x < HID) g_colsum[threadIdx.x] = 0.0f;
}

// ---------------------------------------------------------------------------
// Scatter-add + passthrough + fused column-sums.
// 4 edges per warp -> 4 independent LDG.128 in flight (MLP=4).
// Receiver indices: lanes 0-3 load, shfl-broadcast to the warp.
// colsum(agg) == colsum(edge_attr) over valid edges -> accumulate here.
// ---------------------------------------------------------------------------
__global__ void __launch_bounds__(256) scatter_kernel(
    const float* __restrict__ edge_attr,
    const void* __restrict__ edge_index,
    float* __restrict__ out_edge_attr) {
    __shared__ float s_cs[HID];
    const int t = threadIdx.x;
    if (t < HID) s_cs[t] = 0.0f;
    __syncthreads();

    const int lane = t & 31;
    const int ebase = (blockIdx.x * 8 + (t >> 5)) * 4;  // 800000 % 32 == 0

    long long myidx = 0;
    if (lane < 4) {
        int e = ebase + lane;
        if (g_is64)
            myidx = ((const long long*)edge_index)[(size_t)NEDGES + e];
        else
            myidx = ((const int*)edge_index)[(size_t)NEDGES + e];
    }

    float4 v[4];
#pragma unroll
    for (int i = 0; i < 4; i++)
        v[i] = ((const float4*)(edge_attr + (size_t)(ebase + i) * HID))[lane];

    if (out_edge_attr) {
#pragma unroll
        for (int i = 0; i < 4; i++)
            ((float4*)(out_edge_attr + (size_t)(ebase + i) * HID))[lane] = v[i];
    }

    float4 s = make_float4(0.f, 0.f, 0.f, 0.f);
#pragma unroll
    for (int i = 0; i < 4; i++) {
        long long recv = __shfl_sync(0xffffffffu, myidx, i);
        if (recv < 0 || recv >= NNODES) continue;
        float* dst = g_agg + (size_t)recv * HID + lane * 4;
        asm volatile("red.global.add.v4.f32 [%0], {%1, %2, %3, %4};"
                     :: "l"(dst), "f"(v[i].x), "f"(v[i].y), "f"(v[i].z),
                        "f"(v[i].w)
                     : "memory");
        s.x += v[i].x; s.y += v[i].y; s.z += v[i].z; s.w += v[i].w;
    }

    // per-CTA column sums (8-way smem conflicts acceptable, tiny volume)
    atomicAdd(&s_cs[lane * 4 + 0], s.x);
    atomicAdd(&s_cs[lane * 4 + 1], s.y);
    atomicAdd(&s_cs[lane * 4 + 2], s.z);
    atomicAdd(&s_cs[lane * 4 + 3], s.w);
    __syncthreads();
    if (t < 32) {
        float4 cv = *(float4*)&s_cs[t * 4];
        asm volatile("red.global.add.v4.f32 [%0], {%1, %2, %3, %4};"
                     :: "l"(&g_colsum[t * 4]), "f"(cv.x), "f"(cv.y), "f"(cv.z),
                        "f"(cv.w)
                     : "memory");
    }
}

__global__ void eidx_copy_kernel(const void* __restrict__ ei,
                                 float* __restrict__ out) {
    int total = 2 * NEDGES;
    for (int i = blockIdx.x * blockDim.x + threadIdx.x; i < total;
         i += gridDim.x * blockDim.x) {
        long long v;
        if (g_is64)
            v = ((const long long*)ei)[i];
        else
            v = ((const int*)ei)[i];
        out[i] = (float)v;
    }
}

// b1'[j] = b1[j] - (1/N) * sum_c colsum[c] * W1[128+c][j]
__global__ void b1adj_kernel(const float* __restrict__ W1,
                             const float* __restrict__ b1) {
    int j = threadIdx.x;
    float acc = 0.0f;
#pragma unroll 8
    for (int c = 0; c < HID; c++)
        acc = fmaf(g_colsum[c], W1[(size_t)(HID + c) * HID + j], acc);
    g_b1adj[j] = b1[j] - acc * (1.0f / (float)NNODES);
}

// ---------------------------------------------------------------------------
// Tensor-core GEMM: C[M,128] = act(A[M,K] @ B[K,128] + bias), tf32 mma.sync.
// BM=BN=128, BK=32, 8 warps (2x4), 4x4 m16n8k8 fragments per warp.
// ---------------------------------------------------------------------------
__device__ __forceinline__ float f2tf(float x) {
    uint32_t r;
    asm("cvt.rna.tf32.f32 %0, %1;" : "=r"(r) : "f"(x));
    return __uint_as_float(r);
}

__device__ __forceinline__ void mma_tf32(float* c, const uint32_t* a,
                                         const uint32_t* b) {
    asm volatile(
        "mma.sync.aligned.m16n8k8.row.col.f32.tf32.tf32.f32 "
        "{%0,%1,%2,%3}, {%4,%5,%6,%7}, {%8,%9}, {%0,%1,%2,%3};"
        : "+f"(c[0]), "+f"(c[1]), "+f"(c[2]), "+f"(c[3])
        : "r"(a[0]), "r"(a[1]), "r"(a[2]), "r"(a[3]), "r"(b[0]), "r"(b[1]));
}

template <int K_TOTAL, bool CONCAT, bool RELU>
__global__ void __launch_bounds__(256) gemm_tc_kernel(
    const float* __restrict__ A0, const float* __restrict__ A1,
    const float* __restrict__ B, const float* __restrict__ bias,
    float* __restrict__ C) {
    __shared__ float As[128][36];
    __shared__ float Bs[32][132];

    const int t = threadIdx.x;
    const int w = t >> 5, lane = t & 31;
    const int wm = w >> 2, wn = w & 3;
    const int g = lane >> 2, j = lane & 3;
    const int block_m = blockIdx.x * 128;

    float acc[4][4][4] = {};

    for (int kb = 0; kb < K_TOTAL / 32; kb++) {
        const int kbase = kb * 32;
#pragma unroll
        for (int i = 0; i < 4; i++) {
            int idx = i * 256 + t;
            int row = idx >> 3;
            int c4 = (idx & 7) * 4;
            int gm = block_m + row;
            float4 v = make_float4(0.f, 0.f, 0.f, 0.f);
            if (gm < NNODES) {
                int k = kbase + c4;
                const float* src;
                if (CONCAT)
                    src = (k < HID) ? (A0 + (size_t)gm * HID + k)
                                    : (A1 + (size_t)gm * HID + (k - HID));
                else
                    src = A0 + (size_t)gm * K_TOTAL + k;
                v = *(const float4*)src;
            }
            float4 tv = make_float4(f2tf(v.x), f2tf(v.y), f2tf(v.z), f2tf(v.w));
            *(float4*)&As[row][c4] = tv;
        }
#pragma unroll
        for (int i = 0; i < 4; i++) {
            int idx = i * 256 + t;
            int kr = idx >> 5;
            int c4 = (idx & 31) * 4;
            float4 v = *(const float4*)(B + (size_t)(kbase + kr) * HID + c4);
            float4 tv = make_float4(f2tf(v.x), f2tf(v.y), f2tf(v.z), f2tf(v.w));
            *(float4*)&Bs[kr][c4] = tv;
        }
        __syncthreads();

#pragma unroll
        for (int kk = 0; kk < 4; kk++) {
            const int k0 = kk * 8;
            uint32_t bf[4][2];
#pragma unroll
            for (int nt = 0; nt < 4; nt++) {
                int n0 = wn * 32 + nt * 8 + g;
                bf[nt][0] = __float_as_uint(Bs[k0 + j][n0]);
                bf[nt][1] = __float_as_uint(Bs[k0 + j + 4][n0]);
            }
#pragma unroll
            for (int mt = 0; mt < 4; mt++) {
                int m0 = wm * 64 + mt * 16;
                uint32_t af[4];
                af[0] = __float_as_uint(As[m0 + g][k0 + j]);
                af[1] = __float_as_uint(As[m0 + g + 8][k0 + j]);
                af[2] = __float_as_uint(As[m0 + g][k0 + j + 4]);
                af[3] = __float_as_uint(As[m0 + g + 8][k0 + j + 4]);
#pragma unroll
                for (int nt = 0; nt < 4; nt++) mma_tf32(acc[mt][nt], af, bf[nt]);
            }
        }
        __syncthreads();
    }

#pragma unroll
    for (int mt = 0; mt < 4; mt++) {
#pragma unroll
        for (int half = 0; half < 2; half++) {
            int gm = block_m + wm * 64 + mt * 16 + g + half * 8;
            if (gm >= NNODES) continue;
#pragma unroll
            for (int nt = 0; nt < 4; nt++) {
                int n = wn * 32 + nt * 8 + 2 * j;
                float2 v;
                v.x = acc[mt][nt][half * 2 + 0] + bias[n + 0];
                v.y = acc[mt][nt][half * 2 + 1] + bias[n + 1];
                if (RELU) {
                    v.x = fmaxf(v.x, 0.f);
                    v.y = fmaxf(v.y, 0.f);
                }
                *(float2*)(C + (size_t)gm * HID + n) = v;
            }
        }
    }
}

extern "C" void kernel_launch(void* const* d_in, const int* in_sizes, int n_in,
                              void* d_out, int out_size) {
    const float* node_attr = (const float*)d_in[0];
    const void* edge_index = d_in[1];
    const float* edge_attr = (const float*)d_in[2];
    const float* W1 = (const float*)d_in[3];
    const float* b1 = (const float*)d_in[4];
    const float* W2 = (const float*)d_in[5];
    const float* b2 = (const float*)d_in[6];
    float* out = (float*)d_out;

    float *s_agg, *s_h, *s_b1adj;
    cudaGetSymbolAddress((void**)&s_agg, g_agg);
    cudaGetSymbolAddress((void**)&s_h, g_h);
    cudaGetSymbolAddress((void**)&s_b1adj, g_b1adj);

    const size_t off_ei = (size_t)NNODES * HID;            // 6,400,000
    const size_t off_ea = off_ei + 2ULL * NEDGES;          // 8,000,000
    const size_t full = off_ea + (size_t)NEDGES * HID;     // 110,400,000
    const bool want_ei = (size_t)out_size >= off_ea;
    const bool want_ea = (size_t)out_size >= full;

    detect_kernel<<<1, 256>>>((const int*)edge_index);
    zero_kernel<<<1024, 256>>>();
    scatter_kernel<<<NEDGES / 32, 256>>>(
        edge_attr, edge_index, want_ea ? (out + off_ea) : nullptr);
    if (want_ei) eidx_copy_kernel<<<1024, 256>>>(edge_index, out + off_ei);
    b1adj_kernel<<<1, 128>>>(W1, b1);

    const int mblocks = (NNODES + 127) / 128;  // 391
    gemm_tc_kernel<256, true, true><<<mblocks, 256>>>(node_attr, s_agg, W1,
                                                      s_b1adj, s_h);
    gemm_tc_kernel<128, false, false><<<mblocks, 256>>>(s_h, nullptr, W2, b2,
                                                        out);
}

// round 7
// speedup vs baseline: 1.0374x; 1.0374x over previous
#include <cuda_runtime.h>
#include <cstdint>

#define NNODES 50000
#define NEDGES 800000
#define HID 128

__device__ float g_agg[(size_t)NNODES * HID];
__device__ float g_h[(size_t)NNODES * HID];
__device__ float g_colsum[HID];
__device__ float g_b1adj[HID];
__device__ int g_is64;              // 1 if edge_index is int64
__device__ int g_deg[NNODES];       // receiver degree histogram
__device__ int g_off[NNODES];      // exclusive-scan start offsets
__device__ int g_cursor[NNODES];    // fill cursors
__device__ int g_perm[NEDGES];      // edge ids grouped by receiver

// ---------------------------------------------------------------------------
// Detect edge_index dtype (int64 values < 2^31 have zero odd int32 words).
// ---------------------------------------------------------------------------
__global__ void detect_kernel(const int* __restrict__ ei32) {
    __shared__ int nz;
    if (threadIdx.x == 0) nz = 0;
    __syncthreads();
    int cnt = 0;
    for (int i = threadIdx.x; i < 1024; i += blockDim.x)
        if (ei32[2 * i + 1] != 0) cnt++;
    atomicAdd(&nz, cnt);
    __syncthreads();
    if (threadIdx.x == 0) g_is64 = (nz == 0) ? 1 : 0;
}

__global__ void zero_small_kernel() {
    for (int i = blockIdx.x * blockDim.x + threadIdx.x; i < NNODES;
         i += gridDim.x * blockDim.x)
        g_deg[i] = 0;
    if (blockIdx.x == 0 && threadIdx.x < HID) g_colsum[threadIdx.x] = 0.0f;
}

// ---------------------------------------------------------------------------
// Fused: edge_index -> float passthrough + receiver histogram.
// Positions [NEDGES, 2*NEDGES) are receivers.
// ---------------------------------------------------------------------------
__global__ void eidx_hist_kernel(const void* __restrict__ ei,
                                 float* __restrict__ out) {
    int total = 2 * NEDGES;
    for (int i = blockIdx.x * blockDim.x + threadIdx.x; i < total;
         i += gridDim.x * blockDim.x) {
        long long v;
        if (g_is64)
            v = ((const long long*)ei)[i];
        else
            v = ((const int*)ei)[i];
        if (out) out[i] = (float)v;
        if (i >= NEDGES && v >= 0 && v < NNODES)
            atomicAdd(&g_deg[(int)v], 1);
    }
}

// ---------------------------------------------------------------------------
// Exclusive scan of g_deg -> g_off, g_cursor. One CTA, 1024 threads.
// ---------------------------------------------------------------------------
__global__ void __launch_bounds__(1024) scan_kernel() {
    __shared__ int s[1024];
    const int CH = (NNODES + 1023) / 1024;  // 49
    int t = threadIdx.x;
    int lo = t * CH;
    int hi = lo + CH < NNODES ? lo + CH : NNODES;
    int sum = 0;
    for (int i = lo; i < hi; i++) sum += g_deg[i];
    s[t] = sum;
    __syncthreads();
    for (int d = 1; d < 1024; d <<= 1) {
        int v = (t >= d) ? s[t - d] : 0;
        __syncthreads();
        s[t] += v;
        __syncthreads();
    }
    int run = (t == 0) ? 0 : s[t - 1];
    for (int i = lo; i < hi; i++) {
        g_off[i] = run;
        g_cursor[i] = run;
        run += g_deg[i];
    }
}

// ---------------------------------------------------------------------------
// Fill permutation: group edge ids by receiver (order within a group is
// irrelevant for a sum).
// ---------------------------------------------------------------------------
__global__ void fill_kernel(const void* __restrict__ ei) {
    for (int e = blockIdx.x * blockDim.x + threadIdx.x; e < NEDGES;
         e += gridDim.x * blockDim.x) {
        long long v;
        if (g_is64)
            v = ((const long long*)ei)[(size_t)NEDGES + e];
        else
            v = ((const int*)ei)[(size_t)NEDGES + e];
        if (v < 0 || v >= NNODES) continue;
        int pos = atomicAdd(&g_cursor[(int)v], 1);
        g_perm[pos] = e;
    }
}

// ---------------------------------------------------------------------------
// Gather: one warp per node. Sums its edges' rows (reading edge_attr once),
// writes the passthrough copy from registers, writes agg[n] directly
// (no float atomics anywhere), accumulates column sums.
// ---------------------------------------------------------------------------
__global__ void __launch_bounds__(256) gather_kernel(
    const float* __restrict__ edge_attr,
    float* __restrict__ out_edge_attr) {
    __shared__ float s_cs[HID];
    const int t = threadIdx.x;
    if (t < HID) s_cs[t] = 0.0f;
    __syncthreads();

    const int lane = t & 31;
    const int node = blockIdx.x * 8 + (t >> 5);  // 6250 * 8 == 50000

    float4 acc = make_float4(0.f, 0.f, 0.f, 0.f);
    if (node < NNODES) {
        const int start = g_off[node];
        const int deg = g_deg[node];
        int i = 0;
        for (; i + 2 <= deg; i += 2) {
            int e0 = g_perm[start + i];
            int e1 = g_perm[start + i + 1];
            float4 v0 = ((const float4*)(edge_attr + (size_t)e0 * HID))[lane];
            float4 v1 = ((const float4*)(edge_attr + (size_t)e1 * HID))[lane];
            if (out_edge_attr) {
                ((float4*)(out_edge_attr + (size_t)e0 * HID))[lane] = v0;
                ((float4*)(out_edge_attr + (size_t)e1 * HID))[lane] = v1;
            }
            acc.x += v0.x + v1.x;
            acc.y += v0.y + v1.y;
            acc.z += v0.z + v1.z;
            acc.w += v0.w + v1.w;
        }
        if (i < deg) {
            int e0 = g_perm[start + i];
            float4 v0 = ((const float4*)(edge_attr + (size_t)e0 * HID))[lane];
            if (out_edge_attr)
                ((float4*)(out_edge_attr + (size_t)e0 * HID))[lane] = v0;
            acc.x += v0.x;
            acc.y += v0.y;
            acc.z += v0.z;
            acc.w += v0.w;
        }
        ((float4*)(g_agg + (size_t)node * HID))[lane] = acc;
    }

    atomicAdd(&s_cs[lane * 4 + 0], acc.x);
    atomicAdd(&s_cs[lane * 4 + 1], acc.y);
    atomicAdd(&s_cs[lane * 4 + 2], acc.z);
    atomicAdd(&s_cs[lane * 4 + 3], acc.w);
    __syncthreads();
    if (t < 32) {
        float4 cv = *(float4*)&s_cs[t * 4];
        asm volatile("red.global.add.v4.f32 [%0], {%1, %2, %3, %4};"
                     :: "l"(&g_colsum[t * 4]), "f"(cv.x), "f"(cv.y), "f"(cv.z),
                        "f"(cv.w)
                     : "memory");
    }
}

// b1'[j] = b1[j] - (1/N) * sum_c colsum[c] * W1[128+c][j]
__global__ void b1adj_kernel(const float* __restrict__ W1,
                             const float* __restrict__ b1) {
    int j = threadIdx.x;
    float acc = 0.0f;
#pragma unroll 8
    for (int c = 0; c < HID; c++)
        acc = fmaf(g_colsum[c], W1[(size_t)(HID + c) * HID + j], acc);
    g_b1adj[j] = b1[j] - acc * (1.0f / (float)NNODES);
}

// ---------------------------------------------------------------------------
// Tensor-core GEMM: C[M,128] = act(A[M,K] @ B[K,128] + bias), tf32 mma.sync.
// BM=BN=128, BK=32, 8 warps (2x4), 4x4 m16n8k8 fragments per warp.
// ---------------------------------------------------------------------------
__device__ __forceinline__ float f2tf(float x) {
    uint32_t r;
    asm("cvt.rna.tf32.f32 %0, %1;" : "=r"(r) : "f"(x));
    return __uint_as_float(r);
}

__device__ __forceinline__ void mma_tf32(float* c, const uint32_t* a,
                                         const uint32_t* b) {
    asm volatile(
        "mma.sync.aligned.m16n8k8.row.col.f32.tf32.tf32.f32 "
        "{%0,%1,%2,%3}, {%4,%5,%6,%7}, {%8,%9}, {%0,%1,%2,%3};"
        : "+f"(c[0]), "+f"(c[1]), "+f"(c[2]), "+f"(c[3])
        : "r"(a[0]), "r"(a[1]), "r"(a[2]), "r"(a[3]), "r"(b[0]), "r"(b[1]));
}

template <int K_TOTAL, bool CONCAT, bool RELU>
__global__ void __launch_bounds__(256) gemm_tc_kernel(
    const float* __restrict__ A0, const float* __restrict__ A1,
    const float* __restrict__ B, const float* __restrict__ bias,
    float* __restrict__ C) {
    __shared__ float As[128][36];
    __shared__ float Bs[32][132];

    const int t = threadIdx.x;
    const int w = t >> 5, lane = t & 31;
    const int wm = w >> 2, wn = w & 3;
    const int g = lane >> 2, j = lane & 3;
    const int block_m = blockIdx.x * 128;

    float acc[4][4][4] = {};

    for (int kb = 0; kb < K_TOTAL / 32; kb++) {
        const int kbase = kb * 32;
#pragma unroll
        for (int i = 0; i < 4; i++) {
            int idx = i * 256 + t;
            int row = idx >> 3;
            int c4 = (idx & 7) * 4;
            int gm = block_m + row;
            float4 v = make_float4(0.f, 0.f, 0.f, 0.f);
            if (gm < NNODES) {
                int k = kbase + c4;
                const float* src;
                if (CONCAT)
                    src = (k < HID) ? (A0 + (size_t)gm * HID + k)
                                    : (A1 + (size_t)gm * HID + (k - HID));
                else
                    src = A0 + (size_t)gm * K_TOTAL + k;
                v = *(const float4*)src;
            }
            float4 tv = make_float4(f2tf(v.x), f2tf(v.y), f2tf(v.z), f2tf(v.w));
            *(float4*)&As[row][c4] = tv;
        }
#pragma unroll
        for (int i = 0; i < 4; i++) {
            int idx = i * 256 + t;
            int kr = idx >> 5;
            int c4 = (idx & 31) * 4;
            float4 v = *(const float4*)(B + (size_t)(kbase + kr) * HID + c4);
            float4 tv = make_float4(f2tf(v.x), f2tf(v.y), f2tf(v.z), f2tf(v.w));
            *(float4*)&Bs[kr][c4] = tv;
        }
        __syncthreads();

#pragma unroll
        for (int kk = 0; kk < 4; kk++) {
            const int k0 = kk * 8;
            uint32_t bf[4][2];
#pragma unroll
            for (int nt = 0; nt < 4; nt++) {
                int n0 = wn * 32 + nt * 8 + g;
                bf[nt][0] = __float_as_uint(Bs[k0 + j][n0]);
                bf[nt][1] = __float_as_uint(Bs[k0 + j + 4][n0]);
            }
#pragma unroll
            for (int mt = 0; mt < 4; mt++) {
                int m0 = wm * 64 + mt * 16;
                uint32_t af[4];
                af[0] = __float_as_uint(As[m0 + g][k0 + j]);
                af[1] = __float_as_uint(As[m0 + g + 8][k0 + j]);
                af[2] = __float_as_uint(As[m0 + g][k0 + j + 4]);
                af[3] = __float_as_uint(As[m0 + g + 8][k0 + j + 4]);
#pragma unroll
                for (int nt = 0; nt < 4; nt++) mma_tf32(acc[mt][nt], af, bf[nt]);
            }
        }
        __syncthreads();
    }

#pragma unroll
    for (int mt = 0; mt < 4; mt++) {
#pragma unroll
        for (int half = 0; half < 2; half++) {
            int gm = block_m + wm * 64 + mt * 16 + g + half * 8;
            if (gm >= NNODES) continue;
#pragma unroll
            for (int nt = 0; nt < 4; nt++) {
                int n = wn * 32 + nt * 8 + 2 * j;
                float2 v;
                v.x = acc[mt][nt][half * 2 + 0] + bias[n + 0];
                v.y = acc[mt][nt][half * 2 + 1] + bias[n + 1];
                if (RELU) {
                    v.x = fmaxf(v.x, 0.f);
                    v.y = fmaxf(v.y, 0.f);
                }
                *(float2*)(C + (size_t)gm * HID + n) = v;
            }
        }
    }
}

extern "C" void kernel_launch(void* const* d_in, const int* in_sizes, int n_in,
                              void* d_out, int out_size) {
    const float* node_attr = (const float*)d_in[0];
    const void* edge_index = d_in[1];
    const float* edge_attr = (const float*)d_in[2];
    const float* W1 = (const float*)d_in[3];
    const float* b1 = (const float*)d_in[4];
    const float* W2 = (const float*)d_in[5];
    const float* b2 = (const float*)d_in[6];
    float* out = (float*)d_out;

    float *s_agg, *s_h, *s_b1adj;
    cudaGetSymbolAddress((void**)&s_agg, g_agg);
    cudaGetSymbolAddress((void**)&s_h, g_h);
    cudaGetSymbolAddress((void**)&s_b1adj, g_b1adj);

    const size_t off_ei = (size_t)NNODES * HID;            // 6,400,000
    const size_t off_ea = off_ei + 2ULL * NEDGES;          // 8,000,000
    const size_t full = off_ea + (size_t)NEDGES * HID;     // 110,400,000
    const bool want_ei = (size_t)out_size >= off_ea;
    const bool want_ea = (size_t)out_size >= full;

    detect_kernel<<<1, 256>>>((const int*)edge_index);
    zero_small_kernel<<<64, 256>>>();
    eidx_hist_kernel<<<1024, 256>>>(edge_index,
                                    want_ei ? (out + off_ei) : nullptr);
    scan_kernel<<<1, 1024>>>();
    fill_kernel<<<1024, 256>>>(edge_index);
    gather_kernel<<<NNODES / 8, 256>>>(edge_attr,
                                       want_ea ? (out + off_ea) : nullptr);
    b1adj_kernel<<<1, 128>>>(W1, b1);

    const int mblocks = (NNODES + 127) / 128;  // 391
    gemm_tc_kernel<256, true, true><<<mblocks, 256>>>(node_attr, s_agg, W1,
                                                      s_b1adj, s_h);
    gemm_tc_kernel<128, false, false><<<mblocks, 256>>>(s_h, nullptr, W2, b2,
                                                        out);
}

// round 8
// speedup vs baseline: 1.3217x; 1.2740x over previous
#include <cuda_runtime.h>
#include <cstdint>

#define NNODES 50000
#define NEDGES 800000
#define HID 128

#define SB 512
#define SNB ((NNODES + SB - 1) / SB)  // 98

__device__ float g_agg[(size_t)NNODES * HID];
__device__ float g_h[(size_t)NNODES * HID];
__device__ float g_colsum[HID];
__device__ float g_b1adj[HID];
__device__ int g_is64;              // 1 if edge_index is int64
__device__ int g_deg[NNODES];       // receiver degree histogram
__device__ int g_off[NNODES];       // exclusive-scan start offsets
__device__ int g_cursor[NNODES];    // fill cursors
__device__ int g_perm[NEDGES];      // edge ids grouped by receiver
__device__ int g_bsum[SNB];         // scan block sums

// ---------------------------------------------------------------------------
// Detect edge_index dtype (int64 values < 2^31 have zero odd int32 words).
// ---------------------------------------------------------------------------
__global__ void detect_kernel(const int* __restrict__ ei32) {
    __shared__ int nz;
    if (threadIdx.x == 0) nz = 0;
    __syncthreads();
    int cnt = 0;
    for (int i = threadIdx.x; i < 1024; i += blockDim.x)
        if (ei32[2 * i + 1] != 0) cnt++;
    atomicAdd(&nz, cnt);
    __syncthreads();
    if (threadIdx.x == 0) g_is64 = (nz == 0) ? 1 : 0;
}

__global__ void zero_small_kernel() {
    for (int i = blockIdx.x * blockDim.x + threadIdx.x; i < NNODES;
         i += gridDim.x * blockDim.x)
        g_deg[i] = 0;
    if (blockIdx.x == 0 && threadIdx.x < HID) g_colsum[threadIdx.x] = 0.0f;
}

// ---------------------------------------------------------------------------
// Fused: edge_index -> float passthrough + receiver histogram.
// ---------------------------------------------------------------------------
__global__ void eidx_hist_kernel(const void* __restrict__ ei,
                                 float* __restrict__ out) {
    int total = 2 * NEDGES;
    for (int i = blockIdx.x * blockDim.x + threadIdx.x; i < total;
         i += gridDim.x * blockDim.x) {
        long long v;
        if (g_is64)
            v = ((const long long*)ei)[i];
        else
            v = ((const int*)ei)[i];
        if (out) out[i] = (float)v;
        if (i >= NEDGES && v >= 0 && v < NNODES)
            atomicAdd(&g_deg[(int)v], 1);
    }
}

// ---------------------------------------------------------------------------
// Device-wide exclusive scan, 3 phases (replaces 79us single-CTA scan).
// ---------------------------------------------------------------------------
__global__ void __launch_bounds__(SB) scan1_kernel() {
    __shared__ int s[SB];
    const int b = blockIdx.x, t = threadIdx.x;
    const int i = b * SB + t;
    int v = (i < NNODES) ? g_deg[i] : 0;
    s[t] = v;
    __syncthreads();
    for (int d = 1; d < SB; d <<= 1) {
        int x = (t >= d) ? s[t - d] : 0;
        __syncthreads();
        s[t] += x;
        __syncthreads();
    }
    if (i < NNODES) g_off[i] = s[t] - v;  // local exclusive
    if (t == SB - 1) g_bsum[b] = s[t];
}

__global__ void __launch_bounds__(128) scan2_kernel() {
    __shared__ int sh[128];
    const int t = threadIdx.x;
    int v = (t < SNB) ? g_bsum[t] : 0;
    sh[t] = v;
    __syncthreads();
    for (int d = 1; d < 128; d <<= 1) {
        int x = (t >= d) ? sh[t - d] : 0;
        __syncthreads();
        sh[t] += x;
        __syncthreads();
    }
    if (t < SNB) g_bsum[t] = sh[t] - v;  // exclusive block prefix
}

__global__ void __launch_bounds__(SB) scan3_kernel() {
    const int b = blockIdx.x, t = threadIdx.x;
    const int i = b * SB + t;
    if (i < NNODES) {
        int o = g_off[i] + g_bsum[b];
        g_off[i] = o;
        g_cursor[i] = o;
    }
}

// ---------------------------------------------------------------------------
// Fill permutation: group edge ids by receiver.
// ---------------------------------------------------------------------------
__global__ void fill_kernel(const void* __restrict__ ei) {
    for (int e = blockIdx.x * blockDim.x + threadIdx.x; e < NEDGES;
         e += gridDim.x * blockDim.x) {
        long long v;
        if (g_is64)
            v = ((const long long*)ei)[(size_t)NEDGES + e];
        else
            v = ((const int*)ei)[(size_t)NEDGES + e];
        if (v < 0 || v >= NNODES) continue;
        int pos = atomicAdd(&g_cursor[(int)v], 1);
        g_perm[pos] = e;
    }
}

// ---------------------------------------------------------------------------
// Gather: one warp per node; no float atomics; fused passthrough + colsum.
// ---------------------------------------------------------------------------
__global__ void __launch_bounds__(256) gather_kernel(
    const float* __restrict__ edge_attr,
    float* __restrict__ out_edge_attr) {
    __shared__ float s_cs[HID];
    const int t = threadIdx.x;
    if (t < HID) s_cs[t] = 0.0f;
    __syncthreads();

    const int lane = t & 31;
    const int node = blockIdx.x * 8 + (t >> 5);

    float4 acc = make_float4(0.f, 0.f, 0.f, 0.f);
    if (node < NNODES) {
        const int start = g_off[node];
        const int deg = g_deg[node];
        int i = 0;
        for (; i + 2 <= deg; i += 2) {
            int e0 = g_perm[start + i];
            int e1 = g_perm[start + i + 1];
            float4 v0 = ((const float4*)(edge_attr + (size_t)e0 * HID))[lane];
            float4 v1 = ((const float4*)(edge_attr + (size_t)e1 * HID))[lane];
            if (out_edge_attr) {
                ((float4*)(out_edge_attr + (size_t)e0 * HID))[lane] = v0;
                ((float4*)(out_edge_attr + (size_t)e1 * HID))[lane] = v1;
            }
            acc.x += v0.x + v1.x;
            acc.y += v0.y + v1.y;
            acc.z += v0.z + v1.z;
            acc.w += v0.w + v1.w;
        }
        if (i < deg) {
            int e0 = g_perm[start + i];
            float4 v0 = ((const float4*)(edge_attr + (size_t)e0 * HID))[lane];
            if (out_edge_attr)
                ((float4*)(out_edge_attr + (size_t)e0 * HID))[lane] = v0;
            acc.x += v0.x;
            acc.y += v0.y;
            acc.z += v0.z;
            acc.w += v0.w;
        }
        ((float4*)(g_agg + (size_t)node * HID))[lane] = acc;
    }

    atomicAdd(&s_cs[lane * 4 + 0], acc.x);
    atomicAdd(&s_cs[lane * 4 + 1], acc.y);
    atomicAdd(&s_cs[lane * 4 + 2], acc.z);
    atomicAdd(&s_cs[lane * 4 + 3], acc.w);
    __syncthreads();
    if (t < 32) {
        float4 cv = *(float4*)&s_cs[t * 4];
        asm volatile("red.global.add.v4.f32 [%0], {%1, %2, %3, %4};"
                     :: "l"(&g_colsum[t * 4]), "f"(cv.x), "f"(cv.y), "f"(cv.z),
                        "f"(cv.w)
                     : "memory");
    }
}

// b1'[j] = b1[j] - (1/N) * sum_c colsum[c] * W1[128+c][j]
__global__ void b1adj_kernel(const float* __restrict__ W1,
                             const float* __restrict__ b1) {
    int j = threadIdx.x;
    float acc = 0.0f;
#pragma unroll 8
    for (int c = 0; c < HID; c++)
        acc = fmaf(g_colsum[c], W1[(size_t)(HID + c) * HID + j], acc);
    g_b1adj[j] = b1[j] - acc * (1.0f / (float)NNODES);
}

// ---------------------------------------------------------------------------
// Tensor-core GEMM: C[M,128] = act(A[M,K] @ B[K,128] + bias), tf32 mma.sync.
// BM=BN=128, BK=32, 8 warps (2x4), 4x4 m16n8k8 fragments per warp.
// ---------------------------------------------------------------------------
__device__ __forceinline__ float f2tf(float x) {
    uint32_t r;
    asm("cvt.rna.tf32.f32 %0, %1;" : "=r"(r) : "f"(x));
    return __uint_as_float(r);
}

__device__ __forceinline__ void mma_tf32(float* c, const uint32_t* a,
                                         const uint32_t* b) {
    asm volatile(
        "mma.sync.aligned.m16n8k8.row.col.f32.tf32.tf32.f32 "
        "{%0,%1,%2,%3}, {%4,%5,%6,%7}, {%8,%9}, {%0,%1,%2,%3};"
        : "+f"(c[0]), "+f"(c[1]), "+f"(c[2]), "+f"(c[3])
        : "r"(a[0]), "r"(a[1]), "r"(a[2]), "r"(a[3]), "r"(b[0]), "r"(b[1]));
}

template <int K_TOTAL, bool CONCAT, bool RELU>
__global__ void __launch_bounds__(256) gemm_tc_kernel(
    const float* __restrict__ A0, const float* __restrict__ A1,
    const float* __restrict__ B, const float* __restrict__ bias,
    float* __restrict__ C) {
    __shared__ float As[128][36];
    __shared__ float Bs[32][132];

    const int t = threadIdx.x;
    const int w = t >> 5, lane = t & 31;
    const int wm = w >> 2, wn = w & 3;
    const int g = lane >> 2, j = lane & 3;
    const int block_m = blockIdx.x * 128;

    float acc[4][4][4] = {};

    for (int kb = 0; kb < K_TOTAL / 32; kb++) {
        const int kbase = kb * 32;
#pragma unroll
        for (int i = 0; i < 4; i++) {
            int idx = i * 256 + t;
            int row = idx >> 3;
            int c4 = (idx & 7) * 4;
            int gm = block_m + row;
            float4 v = make_float4(0.f, 0.f, 0.f, 0.f);
            if (gm < NNODES) {
                int k = kbase + c4;
                const float* src;
                if (CONCAT)
                    src = (k < HID) ? (A0 + (size_t)gm * HID + k)
                                    : (A1 + (size_t)gm * HID + (k - HID));
                else
                    src = A0 + (size_t)gm * K_TOTAL + k;
                v = *(const float4*)src;
            }
            float4 tv = make_float4(f2tf(v.x), f2tf(v.y), f2tf(v.z), f2tf(v.w));
            *(float4*)&As[row][c4] = tv;
        }
#pragma unroll
        for (int i = 0; i < 4; i++) {
            int idx = i * 256 + t;
            int kr = idx >> 5;
            int c4 = (idx & 31) * 4;
            float4 v = *(const float4*)(B + (size_t)(kbase + kr) * HID + c4);
            float4 tv = make_float4(f2tf(v.x), f2tf(v.y), f2tf(v.z), f2tf(v.w));
            *(float4*)&Bs[kr][c4] = tv;
        }
        __syncthreads();

#pragma unroll
        for (int kk = 0; kk < 4; kk++) {
            const int k0 = kk * 8;
            uint32_t bf[4][2];
#pragma unroll
            for (int nt = 0; nt < 4; nt++) {
                int n0 = wn * 32 + nt * 8 + g;
                bf[nt][0] = __float_as_uint(Bs[k0 + j][n0]);
                bf[nt][1] = __float_as_uint(Bs[k0 + j + 4][n0]);
            }
#pragma unroll
            for (int mt = 0; mt < 4; mt++) {
                int m0 = wm * 64 + mt * 16;
                uint32_t af[4];
                af[0] = __float_as_uint(As[m0 + g][k0 + j]);
                af[1] = __float_as_uint(As[m0 + g + 8][k0 + j]);
                af[2] = __float_as_uint(As[m0 + g][k0 + j + 4]);
                af[3] = __float_as_uint(As[m0 + g + 8][k0 + j + 4]);
#pragma unroll
                for (int nt = 0; nt < 4; nt++) mma_tf32(acc[mt][nt], af, bf[nt]);
            }
        }
        __syncthreads();
    }

#pragma unroll
    for (int mt = 0; mt < 4; mt++) {
#pragma unroll
        for (int half = 0; half < 2; half++) {
            int gm = block_m + wm * 64 + mt * 16 + g + half * 8;
            if (gm >= NNODES) continue;
#pragma unroll
            for (int nt = 0; nt < 4; nt++) {
                int n = wn * 32 + nt * 8 + 2 * j;
                float2 v;
                v.x = acc[mt][nt][half * 2 + 0] + bias[n + 0];
                v.y = acc[mt][nt][half * 2 + 1] + bias[n + 1];
                if (RELU) {
                    v.x = fmaxf(v.x, 0.f);
                    v.y = fmaxf(v.y, 0.f);
                }
                *(float2*)(C + (size_t)gm * HID + n) = v;
            }
        }
    }
}

extern "C" void kernel_launch(void* const* d_in, const int* in_sizes, int n_in,
                              void* d_out, int out_size) {
    const float* node_attr = (const float*)d_in[0];
    const void* edge_index = d_in[1];
    const float* edge_attr = (const float*)d_in[2];
    const float* W1 = (const float*)d_in[3];
    const float* b1 = (const float*)d_in[4];
    const float* W2 = (const float*)d_in[5];
    const float* b2 = (const float*)d_in[6];
    float* out = (float*)d_out;

    float *s_agg, *s_h, *s_b1adj;
    cudaGetSymbolAddress((void**)&s_agg, g_agg);
    cudaGetSymbolAddress((void**)&s_h, g_h);
    cudaGetSymbolAddress((void**)&s_b1adj, g_b1adj);

    const size_t off_ei = (size_t)NNODES * HID;            // 6,400,000
    const size_t off_ea = off_ei + 2ULL * NEDGES;          // 8,000,000
    const size_t full = off_ea + (size_t)NEDGES * HID;     // 110,400,000
    const bool want_ei = (size_t)out_size >= off_ea;
    const bool want_ea = (size_t)out_size >= full;

    detect_kernel<<<1, 256>>>((const int*)edge_index);
    zero_small_kernel<<<64, 256>>>();
    eidx_hist_kernel<<<1024, 256>>>(edge_index,
                                    want_ei ? (out + off_ei) : nullptr);
    scan1_kernel<<<SNB, SB>>>();
    scan2_kernel<<<1, 128>>>();
    scan3_kernel<<<SNB, SB>>>();
    fill_kernel<<<1024, 256>>>(edge_index);
    gather_kernel<<<NNODES / 8, 256>>>(edge_attr,
                                       want_ea ? (out + off_ea) : nullptr);
    b1adj_kernel<<<1, 128>>>(W1, b1);

    const int mblocks = (NNODES + 127) / 128;  // 391
    gemm_tc_kernel<256, true, true><<<mblocks, 256>>>(node_attr, s_agg, W1,
                                                      s_b1adj, s_h);
    gemm_tc_kernel<128, false, false><<<mblocks, 256>>>(s_h, nullptr, W2, b2,
                                                        out);
}

// round 9
// speedup vs baseline: 1.5194x; 1.1496x over previous
#include <cuda_runtime.h>
#include <cstdint>

#define NNODES 50000
#define NEDGES 800000
#define HID 128

#define SB 512
#define SNB ((NNODES + SB - 1) / SB)  // 98

__device__ float g_agg[(size_t)NNODES * HID];
__device__ float g_colsum[HID];
__device__ float g_b1adj[HID];
__device__ int g_is64;              // 1 if edge_index is int64
__device__ int g_deg[NNODES];       // receiver degree histogram
__device__ int g_off[NNODES];       // exclusive-scan start offsets
__device__ int g_cursor[NNODES];    // fill cursors
__device__ int g_perm[NEDGES];      // edge ids grouped by receiver
__device__ int g_bsum[SNB];         // scan block sums

// ---------------------------------------------------------------------------
// Fused: detect edge_index dtype (block 0) + zero g_deg/g_colsum.
// ---------------------------------------------------------------------------
__global__ void init_kernel(const int* __restrict__ ei32) {
    if (blockIdx.x == 0) {
        __shared__ int nz;
        if (threadIdx.x == 0) nz = 0;
        __syncthreads();
        int cnt = 0;
        for (int i = threadIdx.x; i < 1024; i += blockDim.x)
            if (ei32[2 * i + 1] != 0) cnt++;
        atomicAdd(&nz, cnt);
        __syncthreads();
        if (threadIdx.x == 0) g_is64 = (nz == 0) ? 1 : 0;
        if (threadIdx.x < HID) g_colsum[threadIdx.x] = 0.0f;
    }
    for (int i = blockIdx.x * blockDim.x + threadIdx.x; i < NNODES;
         i += gridDim.x * blockDim.x)
        g_deg[i] = 0;
}

// ---------------------------------------------------------------------------
// Fused: edge_index -> float passthrough + receiver histogram.
// ---------------------------------------------------------------------------
__global__ void eidx_hist_kernel(const void* __restrict__ ei,
                                 float* __restrict__ out) {
    int total = 2 * NEDGES;
    for (int i = blockIdx.x * blockDim.x + threadIdx.x; i < total;
         i += gridDim.x * blockDim.x) {
        long long v;
        if (g_is64)
            v = ((const long long*)ei)[i];
        else
            v = ((const int*)ei)[i];
        if (out) out[i] = (float)v;
        if (i >= NEDGES && v >= 0 && v < NNODES)
            atomicAdd(&g_deg[(int)v], 1);
    }
}

// ---------------------------------------------------------------------------
// Device-wide exclusive scan, 3 phases.
// ---------------------------------------------------------------------------
__global__ void __launch_bounds__(SB) scan1_kernel() {
    __shared__ int s[SB];
    const int b = blockIdx.x, t = threadIdx.x;
    const int i = b * SB + t;
    int v = (i < NNODES) ? g_deg[i] : 0;
    s[t] = v;
    __syncthreads();
    for (int d = 1; d < SB; d <<= 1) {
        int x = (t >= d) ? s[t - d] : 0;
        __syncthreads();
        s[t] += x;
        __syncthreads();
    }
    if (i < NNODES) g_off[i] = s[t] - v;
    if (t == SB - 1) g_bsum[b] = s[t];
}

__global__ void __launch_bounds__(128) scan2_kernel() {
    __shared__ int sh[128];
    const int t = threadIdx.x;
    int v = (t < SNB) ? g_bsum[t] : 0;
    sh[t] = v;
    __syncthreads();
    for (int d = 1; d < 128; d <<= 1) {
        int x = (t >= d) ? sh[t - d] : 0;
        __syncthreads();
        sh[t] += x;
        __syncthreads();
    }
    if (t < SNB) g_bsum[t] = sh[t] - v;
}

__global__ void __launch_bounds__(SB) scan3_kernel() {
    const int b = blockIdx.x, t = threadIdx.x;
    const int i = b * SB + t;
    if (i < NNODES) {
        int o = g_off[i] + g_bsum[b];
        g_off[i] = o;
        g_cursor[i] = o;
    }
}

// ---------------------------------------------------------------------------
// Fill permutation: group edge ids by receiver.
// ---------------------------------------------------------------------------
__global__ void fill_kernel(const void* __restrict__ ei) {
    for (int e = blockIdx.x * blockDim.x + threadIdx.x; e < NEDGES;
         e += gridDim.x * blockDim.x) {
        long long v;
        if (g_is64)
            v = ((const long long*)ei)[(size_t)NEDGES + e];
        else
            v = ((const int*)ei)[(size_t)NEDGES + e];
        if (v < 0 || v >= NNODES) continue;
        int pos = atomicAdd(&g_cursor[(int)v], 1);
        g_perm[pos] = e;
    }
}

// ---------------------------------------------------------------------------
// Gather: one warp per node; no float atomics; fused passthrough + colsum.
// ---------------------------------------------------------------------------
__global__ void __launch_bounds__(256) gather_kernel(
    const float* __restrict__ edge_attr,
    float* __restrict__ out_edge_attr) {
    __shared__ float s_cs[HID];
    const int t = threadIdx.x;
    if (t < HID) s_cs[t] = 0.0f;
    __syncthreads();

    const int lane = t & 31;
    const int node = blockIdx.x * 8 + (t >> 5);

    float4 acc = make_float4(0.f, 0.f, 0.f, 0.f);
    if (node < NNODES) {
        const int start = g_off[node];
        const int deg = g_deg[node];
        int i = 0;
        for (; i + 2 <= deg; i += 2) {
            int e0 = g_perm[start + i];
            int e1 = g_perm[start + i + 1];
            float4 v0 = ((const float4*)(edge_attr + (size_t)e0 * HID))[lane];
            float4 v1 = ((const float4*)(edge_attr + (size_t)e1 * HID))[lane];
            if (out_edge_attr) {
                ((float4*)(out_edge_attr + (size_t)e0 * HID))[lane] = v0;
                ((float4*)(out_edge_attr + (size_t)e1 * HID))[lane] = v1;
            }
            acc.x += v0.x + v1.x;
            acc.y += v0.y + v1.y;
            acc.z += v0.z + v1.z;
            acc.w += v0.w + v1.w;
        }
        if (i < deg) {
            int e0 = g_perm[start + i];
            float4 v0 = ((const float4*)(edge_attr + (size_t)e0 * HID))[lane];
            if (out_edge_attr)
                ((float4*)(out_edge_attr + (size_t)e0 * HID))[lane] = v0;
            acc.x += v0.x;
            acc.y += v0.y;
            acc.z += v0.z;
            acc.w += v0.w;
        }
        ((float4*)(g_agg + (size_t)node * HID))[lane] = acc;
    }

    atomicAdd(&s_cs[lane * 4 + 0], acc.x);
    atomicAdd(&s_cs[lane * 4 + 1], acc.y);
    atomicAdd(&s_cs[lane * 4 + 2], acc.z);
    atomicAdd(&s_cs[lane * 4 + 3], acc.w);
    __syncthreads();
    if (t < 32) {
        float4 cv = *(float4*)&s_cs[t * 4];
        asm volatile("red.global.add.v4.f32 [%0], {%1, %2, %3, %4};"
                     :: "l"(&g_colsum[t * 4]), "f"(cv.x), "f"(cv.y), "f"(cv.z),
                        "f"(cv.w)
                     : "memory");
    }
}

// b1'[j] = b1[j] - (1/N) * sum_c colsum[c] * W1[128+c][j]
__global__ void b1adj_kernel(const float* __restrict__ W1,
                             const float* __restrict__ b1) {
    int j = threadIdx.x;
    float acc = 0.0f;
#pragma unroll 8
    for (int c = 0; c < HID; c++)
        acc = fmaf(g_colsum[c], W1[(size_t)(HID + c) * HID + j], acc);
    g_b1adj[j] = b1[j] - acc * (1.0f / (float)NNODES);
}

// ---------------------------------------------------------------------------
// Fused MLP: x = (relu([node_attr|agg] @ W1 + b1') ) @ W2 + b2, tf32 mma.sync.
// Phase 1: GEMM1 into smem Hs[128][132] (tf32, relu'd).
// Phase 2: GEMM2 from Hs, write out. h never touches global memory.
// BM=BN=128, BK=32, 8 warps (2x4), 4x4 m16n8k8 fragments per warp.
// Dynamic smem ~100.5KB -> 2 CTAs/SM.
// ---------------------------------------------------------------------------
__device__ __forceinline__ float f2tf(float x) {
    uint32_t r;
    asm("cvt.rna.tf32.f32 %0, %1;" : "=r"(r) : "f"(x));
    return __uint_as_float(r);
}

__device__ __forceinline__ void mma_tf32(float* c, const uint32_t* a,
                                         const uint32_t* b) {
    asm volatile(
        "mma.sync.aligned.m16n8k8.row.col.f32.tf32.tf32.f32 "
        "{%0,%1,%2,%3}, {%4,%5,%6,%7}, {%8,%9}, {%0,%1,%2,%3};"
        : "+f"(c[0]), "+f"(c[1]), "+f"(c[2]), "+f"(c[3])
        : "r"(a[0]), "r"(a[1]), "r"(a[2]), "r"(a[3]), "r"(b[0]), "r"(b[1]));
}

#define SMEM_AS 0
#define SMEM_BS (128 * 36)
#define SMEM_HS (128 * 36 + 32 * 132)
#define SMEM_FLOATS (128 * 36 + 32 * 132 + 128 * 132)

__global__ void __launch_bounds__(256) mlp_fused_kernel(
    const float* __restrict__ A0, const float* __restrict__ A1,
    const float* __restrict__ W1, const float* __restrict__ bias1,
    const float* __restrict__ W2, const float* __restrict__ bias2,
    float* __restrict__ C) {
    extern __shared__ float smem[];
    float(*As)[36] = (float(*)[36])(smem + SMEM_AS);
    float(*Bs)[132] = (float(*)[132])(smem + SMEM_BS);
    float(*Hs)[132] = (float(*)[132])(smem + SMEM_HS);

    const int t = threadIdx.x;
    const int w = t >> 5, lane = t & 31;
    const int wm = w >> 2, wn = w & 3;
    const int g = lane >> 2, j = lane & 3;
    const int block_m = blockIdx.x * 128;

    // ===== Phase 1: h = relu([A0|A1] @ W1 + bias1), K=256 =====
    {
        float acc[4][4][4] = {};
        for (int kb = 0; kb < 8; kb++) {
            const int kbase = kb * 32;
#pragma unroll
            for (int i = 0; i < 4; i++) {
                int idx = i * 256 + t;
                int row = idx >> 3;
                int c4 = (idx & 7) * 4;
                int gm = block_m + row;
                float4 v = make_float4(0.f, 0.f, 0.f, 0.f);
                if (gm < NNODES) {
                    int k = kbase + c4;
                    const float* src = (k < HID)
                                           ? (A0 + (size_t)gm * HID + k)
                                           : (A1 + (size_t)gm * HID + (k - HID));
                    v = *(const float4*)src;
                }
                float4 tv =
                    make_float4(f2tf(v.x), f2tf(v.y), f2tf(v.z), f2tf(v.w));
                *(float4*)&As[row][c4] = tv;
            }
#pragma unroll
            for (int i = 0; i < 4; i++) {
                int idx = i * 256 + t;
                int kr = idx >> 5;
                int c4 = (idx & 31) * 4;
                float4 v =
                    *(const float4*)(W1 + (size_t)(kbase + kr) * HID + c4);
                float4 tv =
                    make_float4(f2tf(v.x), f2tf(v.y), f2tf(v.z), f2tf(v.w));
                *(float4*)&Bs[kr][c4] = tv;
            }
            __syncthreads();

#pragma unroll
            for (int kk = 0; kk < 4; kk++) {
                const int k0 = kk * 8;
                uint32_t bf[4][2];
#pragma unroll
                for (int nt = 0; nt < 4; nt++) {
                    int n0 = wn * 32 + nt * 8 + g;
                    bf[nt][0] = __float_as_uint(Bs[k0 + j][n0]);
                    bf[nt][1] = __float_as_uint(Bs[k0 + j + 4][n0]);
                }
#pragma unroll
                for (int mt = 0; mt < 4; mt++) {
                    int m0 = wm * 64 + mt * 16;
                    uint32_t af[4];
                    af[0] = __float_as_uint(As[m0 + g][k0 + j]);
                    af[1] = __float_as_uint(As[m0 + g + 8][k0 + j]);
                    af[2] = __float_as_uint(As[m0 + g][k0 + j + 4]);
                    af[3] = __float_as_uint(As[m0 + g + 8][k0 + j + 4]);
#pragma unroll
                    for (int nt = 0; nt < 4; nt++)
                        mma_tf32(acc[mt][nt], af, bf[nt]);
                }
            }
            __syncthreads();
        }

        // epilogue 1: bias + relu + tf32 -> Hs
#pragma unroll
        for (int mt = 0; mt < 4; mt++) {
#pragma unroll
            for (int half = 0; half < 2; half++) {
                int row = wm * 64 + mt * 16 + g + half * 8;
#pragma unroll
                for (int nt = 0; nt < 4; nt++) {
                    int n = wn * 32 + nt * 8 + 2 * j;
                    float x0 = acc[mt][nt][half * 2 + 0] + bias1[n + 0];
                    float x1 = acc[mt][nt][half * 2 + 1] + bias1[n + 1];
                    Hs[row][n] = f2tf(fmaxf(x0, 0.f));
                    Hs[row][n + 1] = f2tf(fmaxf(x1, 0.f));
                }
            }
        }
        __syncthreads();
    }

    // ===== Phase 2: x = h @ W2 + bias2, K=128, A from Hs =====
    {
        float acc[4][4][4] = {};
        for (int kb = 0; kb < 4; kb++) {
            const int kbase = kb * 32;
#pragma unroll
            for (int i = 0; i < 4; i++) {
                int idx = i * 256 + t;
                int kr = idx >> 5;
                int c4 = (idx & 31) * 4;
                float4 v =
                    *(const float4*)(W2 + (size_t)(kbase + kr) * HID + c4);
                float4 tv =
                    make_float4(f2tf(v.x), f2tf(v.y), f2tf(v.z), f2tf(v.w));
                *(float4*)&Bs[kr][c4] = tv;
            }
            __syncthreads();

#pragma unroll
            for (int kk = 0; kk < 4; kk++) {
                const int k0 = kbase + kk * 8;
                uint32_t bf[4][2];
#pragma unroll
                for (int nt = 0; nt < 4; nt++) {
                    int n0 = wn * 32 + nt * 8 + g;
                    bf[nt][0] = __float_as_uint(Bs[kk * 8 + j][n0]);
                    bf[nt][1] = __float_as_uint(Bs[kk * 8 + j + 4][n0]);
                }
#pragma unroll
                for (int mt = 0; mt < 4; mt++) {
                    int m0 = wm * 64 + mt * 16;
                    uint32_t af[4];
                    af[0] = __float_as_uint(Hs[m0 + g][k0 + j]);
                    af[1] = __float_as_uint(Hs[m0 + g + 8][k0 + j]);
                    af[2] = __float_as_uint(Hs[m0 + g][k0 + j + 4]);
                    af[3] = __float_as_uint(Hs[m0 + g + 8][k0 + j + 4]);
#pragma unroll
                    for (int nt = 0; nt < 4; nt++)
                        mma_tf32(acc[mt][nt], af, bf[nt]);
                }
            }
            __syncthreads();
        }

        // epilogue 2: bias, store
#pragma unroll
        for (int mt = 0; mt < 4; mt++) {
#pragma unroll
            for (int half = 0; half < 2; half++) {
                int gm = block_m + wm * 64 + mt * 16 + g + half * 8;
                if (gm >= NNODES) continue;
#pragma unroll
                for (int nt = 0; nt < 4; nt++) {
                    int n = wn * 32 + nt * 8 + 2 * j;
                    float2 v;
                    v.x = acc[mt][nt][half * 2 + 0] + bias2[n + 0];
                    v.y = acc[mt][nt][half * 2 + 1] + bias2[n + 1];
                    *(float2*)(C + (size_t)gm * HID + n) = v;
                }
            }
        }
    }
}

extern "C" void kernel_launch(void* const* d_in, const int* in_sizes, int n_in,
                              void* d_out, int out_size) {
    const float* node_attr = (const float*)d_in[0];
    const void* edge_index = d_in[1];
    const float* edge_attr = (const float*)d_in[2];
    const float* W1 = (const float*)d_in[3];
    const float* b1 = (const float*)d_in[4];
    const float* W2 = (const float*)d_in[5];
    const float* b2 = (const float*)d_in[6];
    float* out = (float*)d_out;

    float *s_agg, *s_b1adj;
    cudaGetSymbolAddress((void**)&s_agg, g_agg);
    cudaGetSymbolAddress((void**)&s_b1adj, g_b1adj);

    const size_t off_ei = (size_t)NNODES * HID;            // 6,400,000
    const size_t off_ea = off_ei + 2ULL * NEDGES;          // 8,000,000
    const size_t full = off_ea + (size_t)NEDGES * HID;     // 110,400,000
    const bool want_ei = (size_t)out_size >= off_ea;
    const bool want_ea = (size_t)out_size >= full;

    const int smem_bytes = SMEM_FLOATS * 4;  // ~100.5 KB
    cudaFuncSetAttribute(mlp_fused_kernel,
                         cudaFuncAttributeMaxDynamicSharedMemorySize,
                         smem_bytes);

    init_kernel<<<64, 256>>>((const int*)edge_index);
    eidx_hist_kernel<<<1024, 256>>>(edge_index,
                                    want_ei ? (out + off_ei) : nullptr);
    scan1_kernel<<<SNB, SB>>>();
    scan2_kernel<<<1, 128>>>();
    scan3_kernel<<<SNB, SB>>>();
    fill_kernel<<<1024, 256>>>(edge_index);
    gather_kernel<<<NNODES / 8, 256>>>(edge_attr,
                                       want_ea ? (out + off_ea) : nullptr);
    b1adj_kernel<<<1, 128>>>(W1, b1);

    const int mblocks = (NNODES + 127) / 128;  // 391
    mlp_fused_kernel<<<mblocks, 256, smem_bytes>>>(node_attr, s_agg, W1,
                                                   s_b1adj, W2, b2, out);
}